// round 1
// baseline (speedup 1.0000x reference)
#include <cuda_runtime.h>
#include <cstdint>

#define B_  32
#define T_  1024
#define H_  384
#define M_  4096
#define MEL_MAX 4096

// Scratch (static device allocations are the sanctioned workaround)
__device__ int g_idx[B_ * M_];   // token index per output frame, -1 = masked

// ---------------------------------------------------------------------------
// Kernel A: per-batch cumsum of durations, dec_lens, frame->token index map.
// grid = B_, block = 1024
// ---------------------------------------------------------------------------
__global__ void prep_kernel(const int* __restrict__ durations,
                            float* __restrict__ out /* full out buffer */) {
    __shared__ int csum[T_];
    const int b = blockIdx.x;
    const int tid = threadIdx.x;

    // load durations (reps = round(dur / 1.0) = dur)
    csum[tid] = durations[b * T_ + tid];
    __syncthreads();

    // Hillis-Steele inclusive scan over 1024 elements
    #pragma unroll
    for (int off = 1; off < T_; off <<= 1) {
        int v = csum[tid];
        int add = (tid >= off) ? csum[tid - off] : 0;
        __syncthreads();
        csum[tid] = v + add;
        __syncthreads();
    }

    const int total = csum[T_ - 1];
    const int dec = total < MEL_MAX ? total : MEL_MAX;

    if (tid == 0) {
        // dec_lens appended after len_regulated, converted to output dtype f32
        out[(size_t)B_ * M_ * H_ + b] = (float)dec;
    }

    // Each thread resolves 4 output frames via binary search (upper_bound)
    #pragma unroll
    for (int r = 0; r < M_ / T_; ++r) {
        const int j = tid + r * T_;
        int result;
        if (j >= dec) {
            result = -1;  // masked frame -> zeros
        } else {
            int lo = 0, hi = T_;
            while (lo < hi) {
                int mid = (lo + hi) >> 1;
                if (csum[mid] <= j) lo = mid + 1; else hi = mid;
            }
            result = lo < (T_ - 1) ? lo : (T_ - 1);
        }
        g_idx[b * M_ + j] = result;
    }
}

// ---------------------------------------------------------------------------
// Kernel B: fused conv-conditioning + gather + mask.
// block = (96, 4): x indexes 4-channel float4 groups, y indexes rows.
// grid = B_*M_/4 blocks.
// ---------------------------------------------------------------------------
__global__ __launch_bounds__(384)
void gather_kernel(const float* __restrict__ enc,     // [B,T,H]
                   const float* __restrict__ pitch,   // [B,1,T]
                   const float* __restrict__ energy,  // [B,1,T]
                   const float* __restrict__ pw,      // [H,1,3]
                   const float* __restrict__ pb,      // [H]
                   const float* __restrict__ ew,      // [H,1,3]
                   const float* __restrict__ eb,      // [H]
                   float* __restrict__ out) {         // [B,M,H] (+B tail)
    // smem: weight arrays laid out channel-contiguous for float4 reads
    __shared__ float s_pw0[H_], s_pw1[H_], s_pw2[H_];
    __shared__ float s_ew0[H_], s_ew1[H_], s_ew2[H_];
    __shared__ float s_bias[H_];  // pb + eb combined

    const int tx = threadIdx.x;            // 0..95
    const int ty = threadIdx.y;            // 0..3
    const int lin = ty * 96 + tx;          // 0..383

    // cooperative weight preload: one channel per thread
    {
        const int c = lin;
        s_pw0[c] = pw[c * 3 + 0];
        s_pw1[c] = pw[c * 3 + 1];
        s_pw2[c] = pw[c * 3 + 2];
        s_ew0[c] = ew[c * 3 + 0];
        s_ew1[c] = ew[c * 3 + 1];
        s_ew2[c] = ew[c * 3 + 2];
        s_bias[c] = pb[c] + eb[c];
    }
    __syncthreads();

    const int row = blockIdx.x * 4 + ty;   // global (b, j) row
    const int b = row >> 12;               // / 4096
    const int idx = g_idx[row];

    const int c0 = tx * 4;
    float4* outp = (float4*)(out + (size_t)row * H_ + c0);

    if (idx < 0) {
        *outp = make_float4(0.f, 0.f, 0.f, 0.f);
        return;
    }

    const int t = idx;
    const int pbase = b * T_;
    // conv SAME window (zero pad at edges)
    const float pm1 = (t > 0)      ? __ldg(pitch  + pbase + t - 1) : 0.f;
    const float p0  =                __ldg(pitch  + pbase + t);
    const float pp1 = (t < T_ - 1) ? __ldg(pitch  + pbase + t + 1) : 0.f;
    const float em1 = (t > 0)      ? __ldg(energy + pbase + t - 1) : 0.f;
    const float e0  =                __ldg(energy + pbase + t);
    const float ep1 = (t < T_ - 1) ? __ldg(energy + pbase + t + 1) : 0.f;

    const float4 ev = *(const float4*)(enc + ((size_t)b * T_ + t) * H_ + c0);

    const float4 w0 = *(const float4*)(s_pw0 + c0);
    const float4 w1 = *(const float4*)(s_pw1 + c0);
    const float4 w2 = *(const float4*)(s_pw2 + c0);
    const float4 u0 = *(const float4*)(s_ew0 + c0);
    const float4 u1 = *(const float4*)(s_ew1 + c0);
    const float4 u2 = *(const float4*)(s_ew2 + c0);
    const float4 bi = *(const float4*)(s_bias + c0);

    float4 r;
    r.x = ev.x + bi.x + pm1 * w0.x + p0 * w1.x + pp1 * w2.x
               + em1 * u0.x + e0 * u1.x + ep1 * u2.x;
    r.y = ev.y + bi.y + pm1 * w0.y + p0 * w1.y + pp1 * w2.y
               + em1 * u0.y + e0 * u1.y + ep1 * u2.y;
    r.z = ev.z + bi.z + pm1 * w0.z + p0 * w1.z + pp1 * w2.z
               + em1 * u0.z + e0 * u1.z + ep1 * u2.z;
    r.w = ev.w + bi.w + pm1 * w0.w + p0 * w1.w + pp1 * w2.w
               + em1 * u0.w + e0 * u1.w + ep1 * u2.w;
    *outp = r;
}

// ---------------------------------------------------------------------------
// Inputs (metadata order = setup_inputs order):
//   0 enc_out  [B,T,H] f32
//   1 pitch    [B,1,T] f32
//   2 energy   [B,1,T] f32
//   3 pitch_w  [H,1,3] f32
//   4 pitch_b  [H]     f32
//   5 energy_w [H,1,3] f32
//   6 energy_b [H]     f32
//   7 durations[B,T]   i32
// Output: len_regulated [B,M,H] f32 followed by dec_lens [B] (as f32)
// ---------------------------------------------------------------------------
extern "C" void kernel_launch(void* const* d_in, const int* in_sizes, int n_in,
                              void* d_out, int out_size) {
    const float* enc    = (const float*)d_in[0];
    const float* pitch  = (const float*)d_in[1];
    const float* energy = (const float*)d_in[2];
    const float* pw     = (const float*)d_in[3];
    const float* pb     = (const float*)d_in[4];
    const float* ew     = (const float*)d_in[5];
    const float* eb     = (const float*)d_in[6];
    const int*   dur    = (const int*)d_in[7];
    float* out = (float*)d_out;

    prep_kernel<<<B_, T_>>>(dur, out);

    dim3 blk(96, 4);
    gather_kernel<<<(B_ * M_) / 4, blk>>>(enc, pitch, energy, pw, pb, ew, eb, out);
}

// round 4
// speedup vs baseline: 2.3222x; 2.3222x over previous
#include <cuda_runtime.h>
#include <cstdint>

#define B_  32
#define T_  1024
#define H_  384
#define M_  4096
#define MEL_MAX 4096
#define FRAMES 64              // frames per block
#define FPT 16                 // frames per thread (FRAMES / blockDim.y)

// Scratch (__device__ globals are the sanctioned workaround for no-alloc rule)
__device__ int    g_idx[B_ * M_];        // token index per output frame, -1 = masked
__device__ float4 g_win[B_ * T_ * 2];    // per-token conv windows: {pm1,p0,pp1,em1} {e0,ep1,0,0}

// ---------------------------------------------------------------------------
// Kernel A: per-batch cumsum, dec_lens, frame->token map, conv windows.
// grid = B_, block = 1024
// ---------------------------------------------------------------------------
__global__ void prep_kernel(const int* __restrict__ durations,
                            const float* __restrict__ pitch,
                            const float* __restrict__ energy,
                            float* __restrict__ out) {
    __shared__ int csum[T_];
    const int b = blockIdx.x;
    const int tid = threadIdx.x;

    csum[tid] = durations[b * T_ + tid];

    // conv windows (SAME padding, K=3)
    {
        const int base = b * T_;
        const float pm1 = (tid > 0)      ? pitch [base + tid - 1] : 0.f;
        const float p0  =                  pitch [base + tid];
        const float pp1 = (tid < T_ - 1) ? pitch [base + tid + 1] : 0.f;
        const float em1 = (tid > 0)      ? energy[base + tid - 1] : 0.f;
        const float e0  =                  energy[base + tid];
        const float ep1 = (tid < T_ - 1) ? energy[base + tid + 1] : 0.f;
        g_win[(base + tid) * 2 + 0] = make_float4(pm1, p0, pp1, em1);
        g_win[(base + tid) * 2 + 1] = make_float4(e0, ep1, 0.f, 0.f);
    }
    __syncthreads();

    // Hillis-Steele inclusive scan (1024)
    #pragma unroll
    for (int off = 1; off < T_; off <<= 1) {
        int v = csum[tid];
        int add = (tid >= off) ? csum[tid - off] : 0;
        __syncthreads();
        csum[tid] = v + add;
        __syncthreads();
    }

    const int total = csum[T_ - 1];
    const int dec = total < MEL_MAX ? total : MEL_MAX;

    if (tid == 0)
        out[(size_t)B_ * M_ * H_ + b] = (float)dec;   // dec_lens tail (f32 output dtype)

    #pragma unroll
    for (int r = 0; r < M_ / T_; ++r) {
        const int j = tid + r * T_;
        int result;
        if (j >= dec) {
            result = -1;
        } else {
            int lo = 0, hi = T_;
            while (lo < hi) {
                int mid = (lo + hi) >> 1;
                if (csum[mid] <= j) lo = mid + 1; else hi = mid;
            }
            result = lo < (T_ - 1) ? lo : (T_ - 1);
        }
        g_idx[b * M_ + j] = result;
    }
}

// ---------------------------------------------------------------------------
// Kernel B: fused conv-conditioning + gather + mask, register-resident weights,
// token-run result reuse, streaming stores.
// block = (96, 4): tx = float4 channel group, ty = frame sub-chunk.
// Each thread handles FPT=16 consecutive frames of one channel group.
// grid = B_*M_/FRAMES = 2048
// ---------------------------------------------------------------------------
__global__ __launch_bounds__(384)
void gather_kernel(const float* __restrict__ enc,     // [B,T,H]
                   const float* __restrict__ pw,      // [H,1,3]
                   const float* __restrict__ pb,      // [H]
                   const float* __restrict__ ew,      // [H,1,3]
                   const float* __restrict__ eb,      // [H]
                   float* __restrict__ out) {         // [B,M,H] (+B tail)
    __shared__ float s_pw0[H_], s_pw1[H_], s_pw2[H_];
    __shared__ float s_ew0[H_], s_ew1[H_], s_ew2[H_];
    __shared__ float s_bias[H_];
    __shared__ int   s_idx[FRAMES];

    const int tx  = threadIdx.x;          // 0..95
    const int ty  = threadIdx.y;          // 0..3
    const int lin = ty * 96 + tx;         // 0..383

    // stage weights to smem (once per block), channel-contiguous
    {
        const int c = lin;
        s_pw0[c] = pw[c * 3 + 0];
        s_pw1[c] = pw[c * 3 + 1];
        s_pw2[c] = pw[c * 3 + 2];
        s_ew0[c] = ew[c * 3 + 0];
        s_ew1[c] = ew[c * 3 + 1];
        s_ew2[c] = ew[c * 3 + 2];
        s_bias[c] = pb[c] + eb[c];
    }

    const int b         = blockIdx.x >> 6;           // / (M_/FRAMES)
    const int frameBase = (blockIdx.x & 63) * FRAMES;

    if (lin < FRAMES)
        s_idx[lin] = g_idx[b * M_ + frameBase + lin];
    __syncthreads();

    const int c0 = tx * 4;
    // weights -> registers, once per thread
    const float4 w0 = *(const float4*)(s_pw0 + c0);
    const float4 w1 = *(const float4*)(s_pw1 + c0);
    const float4 w2 = *(const float4*)(s_pw2 + c0);
    const float4 u0 = *(const float4*)(s_ew0 + c0);
    const float4 u1 = *(const float4*)(s_ew1 + c0);
    const float4 u2 = *(const float4*)(s_ew2 + c0);
    const float4 bi = *(const float4*)(s_bias + c0);

    const size_t outBase = ((size_t)b * M_ + frameBase + ty * FPT) * H_ + c0;
    const int    sBase   = ty * FPT;

    int last_t = -2;
    float4 r = make_float4(0.f, 0.f, 0.f, 0.f);

    #pragma unroll 4
    for (int f = 0; f < FPT; ++f) {
        const int idx = s_idx[sBase + f];
        float* outp = out + outBase + (size_t)f * H_;

        if (idx < 0) {
            const float4 z = make_float4(0.f, 0.f, 0.f, 0.f);
            __stwt((float4*)outp, z);
            continue;
        }
        if (idx != last_t) {
            last_t = idx;
            const float4 win0 = g_win[(b * T_ + idx) * 2 + 0]; // pm1,p0,pp1,em1
            const float4 win1 = g_win[(b * T_ + idx) * 2 + 1]; // e0,ep1,-,-
            const float4 ev = *(const float4*)(enc + ((size_t)b * T_ + idx) * H_ + c0);
            r.x = ev.x + bi.x + win0.x * w0.x + win0.y * w1.x + win0.z * w2.x
                       + win0.w * u0.x + win1.x * u1.x + win1.y * u2.x;
            r.y = ev.y + bi.y + win0.x * w0.y + win0.y * w1.y + win0.z * w2.y
                       + win0.w * u0.y + win1.x * u1.y + win1.y * u2.y;
            r.z = ev.z + bi.z + win0.x * w0.z + win0.y * w1.z + win0.z * w2.z
                       + win0.w * u0.z + win1.x * u1.z + win1.y * u2.z;
            r.w = ev.w + bi.w + win0.x * w0.w + win0.y * w1.w + win0.z * w2.w
                       + win0.w * u0.w + win1.x * u1.w + win1.y * u2.w;
        }
        __stwt((float4*)outp, r);
    }
}

// ---------------------------------------------------------------------------
// Inputs: 0 enc [B,T,H] f32 | 1 pitch [B,1,T] | 2 energy [B,1,T]
//         3 pitch_w [H,1,3] | 4 pitch_b [H] | 5 energy_w [H,1,3] | 6 energy_b [H]
//         7 durations [B,T] i32
// Output: len_regulated [B,M,H] f32 followed by dec_lens [B] (as f32)
// ---------------------------------------------------------------------------
extern "C" void kernel_launch(void* const* d_in, const int* in_sizes, int n_in,
                              void* d_out, int out_size) {
    const float* enc    = (const float*)d_in[0];
    const float* pitch  = (const float*)d_in[1];
    const float* energy = (const float*)d_in[2];
    const float* pw     = (const float*)d_in[3];
    const float* pb     = (const float*)d_in[4];
    const float* ew     = (const float*)d_in[5];
    const float* eb     = (const float*)d_in[6];
    const int*   dur    = (const int*)d_in[7];
    float* out = (float*)d_out;

    prep_kernel<<<B_, T_>>>(dur, pitch, energy, out);

    dim3 blk(96, 4);
    gather_kernel<<<(B_ * M_) / FRAMES, blk>>>(enc, pw, pb, ew, eb, out);
}

// round 5
// speedup vs baseline: 2.4830x; 1.0693x over previous
#include <cuda_runtime.h>
#include <cstdint>

#define B_  32
#define T_  1024
#define H_  384
#define M_  4096
#define MEL_MAX 4096

// __device__ scratch (sanctioned no-alloc workaround)
__device__ int g_csum[B_ * T_];   // inclusive cumsum of durations
__device__ int g_dec[B_];         // dec_lens

// ---------------------------------------------------------------------------
// Kernel A: per-batch scan of durations (shfl two-level), dec_lens.
// grid = B_, block = 1024
// ---------------------------------------------------------------------------
__global__ void prep_kernel(const int* __restrict__ durations,
                            float* __restrict__ out) {
    __shared__ int warpsum[32];
    const int b    = blockIdx.x;
    const int tid  = threadIdx.x;
    const int lane = tid & 31;
    const int wid  = tid >> 5;

    int v = durations[b * T_ + tid];

    // inclusive warp scan
    #pragma unroll
    for (int off = 1; off < 32; off <<= 1) {
        int n = __shfl_up_sync(0xffffffffu, v, off);
        if (lane >= off) v += n;
    }
    if (lane == 31) warpsum[wid] = v;
    __syncthreads();

    if (wid == 0) {
        int s = warpsum[lane];
        #pragma unroll
        for (int off = 1; off < 32; off <<= 1) {
            int n = __shfl_up_sync(0xffffffffu, s, off);
            if (lane >= off) s += n;
        }
        warpsum[lane] = s;
    }
    __syncthreads();

    const int csum = v + (wid > 0 ? warpsum[wid - 1] : 0);
    g_csum[b * T_ + tid] = csum;

    if (tid == T_ - 1) {
        const int dec = csum < MEL_MAX ? csum : MEL_MAX;
        g_dec[b] = dec;
        out[(size_t)B_ * M_ * H_ + b] = (float)dec;   // dec_lens tail (f32)
    }
}

// ---------------------------------------------------------------------------
// Kernel B: token->frames scatter. block (96,4): ty = token, tx = channel grp.
// All 32 lanes of a warp share one token -> uniform run, no divergence.
// grid = (T_/4, B_)
// ---------------------------------------------------------------------------
__global__ __launch_bounds__(384)
void scatter_kernel(const float* __restrict__ enc,     // [B,T,H]
                    const float* __restrict__ pitch,   // [B,1,T]
                    const float* __restrict__ energy,  // [B,1,T]
                    const float* __restrict__ pw,      // [H,1,3]
                    const float* __restrict__ pb,      // [H]
                    const float* __restrict__ ew,      // [H,1,3]
                    const float* __restrict__ eb,      // [H]
                    float* __restrict__ out) {         // [B,M,H] (+B tail)
    __shared__ float s_pw0[H_], s_pw1[H_], s_pw2[H_];
    __shared__ float s_ew0[H_], s_ew1[H_], s_ew2[H_];
    __shared__ float s_bias[H_];

    const int tx  = threadIdx.x;          // 0..95
    const int ty  = threadIdx.y;          // 0..3
    const int lin = ty * 96 + tx;

    {   // stage weights once per block (coalesced)
        const int c = lin;
        s_pw0[c] = pw[c * 3 + 0];
        s_pw1[c] = pw[c * 3 + 1];
        s_pw2[c] = pw[c * 3 + 2];
        s_ew0[c] = ew[c * 3 + 0];
        s_ew1[c] = ew[c * 3 + 1];
        s_ew2[c] = ew[c * 3 + 2];
        s_bias[c] = pb[c] + eb[c];
    }
    __syncthreads();

    const int b = blockIdx.y;
    const int t = blockIdx.x * 4 + ty;

    const int dec  = g_dec[b];
    const int cend = g_csum[b * T_ + t];
    const int start = (t > 0) ? g_csum[b * T_ + t - 1] : 0;
    const int end   = cend < dec ? cend : dec;
    if (start >= end) return;             // warp-uniform exit (reps==0 or past dec)

    // conv window scalars (warp-uniform broadcast loads)
    const int pbase = b * T_;
    const float pm1 = (t > 0)      ? __ldg(pitch  + pbase + t - 1) : 0.f;
    const float p0  =                __ldg(pitch  + pbase + t);
    const float pp1 = (t < T_ - 1) ? __ldg(pitch  + pbase + t + 1) : 0.f;
    const float em1 = (t > 0)      ? __ldg(energy + pbase + t - 1) : 0.f;
    const float e0  =                __ldg(energy + pbase + t);
    const float ep1 = (t < T_ - 1) ? __ldg(energy + pbase + t + 1) : 0.f;

    const int c0 = tx * 4;
    const float4 ev = *(const float4*)(enc + ((size_t)b * T_ + t) * H_ + c0);

    const float4 w0 = *(const float4*)(s_pw0 + c0);
    const float4 w1 = *(const float4*)(s_pw1 + c0);
    const float4 w2 = *(const float4*)(s_pw2 + c0);
    const float4 u0 = *(const float4*)(s_ew0 + c0);
    const float4 u1 = *(const float4*)(s_ew1 + c0);
    const float4 u2 = *(const float4*)(s_ew2 + c0);
    const float4 bi = *(const float4*)(s_bias + c0);

    float4 r;
    r.x = ev.x + bi.x + pm1 * w0.x + p0 * w1.x + pp1 * w2.x
               + em1 * u0.x + e0 * u1.x + ep1 * u2.x;
    r.y = ev.y + bi.y + pm1 * w0.y + p0 * w1.y + pp1 * w2.y
               + em1 * u0.y + e0 * u1.y + ep1 * u2.y;
    r.z = ev.z + bi.z + pm1 * w0.z + p0 * w1.z + pp1 * w2.z
               + em1 * u0.z + e0 * u1.z + ep1 * u2.z;
    r.w = ev.w + bi.w + pm1 * w0.w + p0 * w1.w + pp1 * w2.w
               + em1 * u0.w + e0 * u1.w + ep1 * u2.w;

    // stream the run: independent stores, consecutive rows
    float* outp = out + ((size_t)b * M_ + start) * H_ + c0;
    for (int j = start; j < end; ++j) {
        __stwt((float4*)outp, r);
        outp += H_;
    }
}

// ---------------------------------------------------------------------------
// Kernel C: zero-fill masked rows [dec, M). Mostly early-exit blocks.
// grid = (M_/16, B_), block (96,4): each thread 4 rows (stride 4) x 1 float4.
// ---------------------------------------------------------------------------
__global__ __launch_bounds__(384)
void zero_kernel(float* __restrict__ out) {
    const int b = blockIdx.y;
    const int rowBase = blockIdx.x * 16;
    const int dec = g_dec[b];
    if (rowBase + 16 <= dec) return;      // fully inside valid region

    const int tx = threadIdx.x;
    const int ty = threadIdx.y;
    const int c0 = tx * 4;
    const float4 z = make_float4(0.f, 0.f, 0.f, 0.f);

    #pragma unroll
    for (int rr = 0; rr < 4; ++rr) {
        const int row = rowBase + ty + rr * 4;
        if (row >= dec) {
            __stwt((float4*)(out + ((size_t)b * M_ + row) * H_ + c0), z);
        }
    }
}

// ---------------------------------------------------------------------------
// Inputs: 0 enc [B,T,H] f32 | 1 pitch [B,1,T] | 2 energy [B,1,T]
//         3 pitch_w [H,1,3] | 4 pitch_b [H] | 5 energy_w [H,1,3] | 6 energy_b [H]
//         7 durations [B,T] i32
// Output: len_regulated [B,M,H] f32 followed by dec_lens [B] (as f32)
// ---------------------------------------------------------------------------
extern "C" void kernel_launch(void* const* d_in, const int* in_sizes, int n_in,
                              void* d_out, int out_size) {
    const float* enc    = (const float*)d_in[0];
    const float* pitch  = (const float*)d_in[1];
    const float* energy = (const float*)d_in[2];
    const float* pw     = (const float*)d_in[3];
    const float* pb     = (const float*)d_in[4];
    const float* ew     = (const float*)d_in[5];
    const float* eb     = (const float*)d_in[6];
    const int*   dur    = (const int*)d_in[7];
    float* out = (float*)d_out;

    prep_kernel<<<B_, T_>>>(dur, out);

    dim3 blk(96, 4);
    dim3 sgrid(T_ / 4, B_);
    scatter_kernel<<<sgrid, blk>>>(enc, pitch, energy, pw, pb, ew, eb, out);

    dim3 zgrid(M_ / 16, B_);
    zero_kernel<<<zgrid, blk>>>(out);
}

// round 6
// speedup vs baseline: 2.6306x; 1.0595x over previous
#include <cuda_runtime.h>
#include <cstdint>

#define B_  32
#define T_  1024
#define H_  384
#define M_  4096
#define MEL_MAX 4096
#define SCAT_BLKS (T_ / 4)    // 256 scatter blocks per batch
#define ZERO_BLKS (M_ / 16)   // 256 zero blocks per batch

// __device__ scratch (sanctioned no-alloc workaround)
__device__ int g_csum[B_ * T_];   // inclusive cumsum of durations
__device__ int g_dec[B_];         // dec_lens

// ---------------------------------------------------------------------------
// Kernel A: per-batch scan of durations (shfl two-level), dec_lens.
// grid = B_, block = 1024
// ---------------------------------------------------------------------------
__global__ void prep_kernel(const int* __restrict__ durations,
                            float* __restrict__ out) {
    __shared__ int warpsum[32];
    const int b    = blockIdx.x;
    const int tid  = threadIdx.x;
    const int lane = tid & 31;
    const int wid  = tid >> 5;

    int v = durations[b * T_ + tid];

    #pragma unroll
    for (int off = 1; off < 32; off <<= 1) {
        int n = __shfl_up_sync(0xffffffffu, v, off);
        if (lane >= off) v += n;
    }
    if (lane == 31) warpsum[wid] = v;
    __syncthreads();

    if (wid == 0) {
        int s = warpsum[lane];
        #pragma unroll
        for (int off = 1; off < 32; off <<= 1) {
            int n = __shfl_up_sync(0xffffffffu, s, off);
            if (lane >= off) s += n;
        }
        warpsum[lane] = s;
    }
    __syncthreads();

    const int csum = v + (wid > 0 ? warpsum[wid - 1] : 0);
    g_csum[b * T_ + tid] = csum;

    if (tid == T_ - 1) {
        const int dec = csum < MEL_MAX ? csum : MEL_MAX;
        g_dec[b] = dec;
        out[(size_t)B_ * M_ * H_ + b] = (float)dec;   // dec_lens tail (f32)
    }
}

// ---------------------------------------------------------------------------
// Kernel B (fused): scatter + zero-fill in one launch.
// grid = (SCAT_BLKS + ZERO_BLKS, B_), block (96,4).
//   blockIdx.x <  SCAT_BLKS : token->frames scatter (ty = token, tx = chan grp)
//   blockIdx.x >= SCAT_BLKS : zero rows [dec, M) (16 rows per block)
// ---------------------------------------------------------------------------
__global__ __launch_bounds__(384)
void fused_kernel(const float* __restrict__ enc,     // [B,T,H]
                  const float* __restrict__ pitch,   // [B,1,T]
                  const float* __restrict__ energy,  // [B,1,T]
                  const float* __restrict__ pw,      // [H,1,3]
                  const float* __restrict__ pb,      // [H]
                  const float* __restrict__ ew,      // [H,1,3]
                  const float* __restrict__ eb,      // [H]
                  float* __restrict__ out) {         // [B,M,H] (+B tail)
    const int b  = blockIdx.y;
    const int tx = threadIdx.x;          // 0..95
    const int ty = threadIdx.y;          // 0..3
    const int c0 = tx * 4;

    if (blockIdx.x >= SCAT_BLKS) {
        // ---------------- zero role: rows [dec, M) ----------------
        const int rowBase = (blockIdx.x - SCAT_BLKS) * 16;
        const int dec = g_dec[b];
        if (rowBase + 16 <= dec) return;          // fully valid region

        const float4 z = make_float4(0.f, 0.f, 0.f, 0.f);
        #pragma unroll
        for (int rr = 0; rr < 4; ++rr) {
            const int row = rowBase + ty + rr * 4;
            if (row >= dec)
                __stwt((float4*)(out + ((size_t)b * M_ + row) * H_ + c0), z);
        }
        return;
    }

    // ---------------- scatter role ----------------
    __shared__ float s_pw0[H_], s_pw1[H_], s_pw2[H_];
    __shared__ float s_ew0[H_], s_ew1[H_], s_ew2[H_];
    __shared__ float s_bias[H_];

    const int lin = ty * 96 + tx;
    {   // stage weights once per block (coalesced)
        const int c = lin;
        s_pw0[c] = pw[c * 3 + 0];
        s_pw1[c] = pw[c * 3 + 1];
        s_pw2[c] = pw[c * 3 + 2];
        s_ew0[c] = ew[c * 3 + 0];
        s_ew1[c] = ew[c * 3 + 1];
        s_ew2[c] = ew[c * 3 + 2];
        s_bias[c] = pb[c] + eb[c];
    }
    __syncthreads();

    const int t = blockIdx.x * 4 + ty;

    const int dec   = g_dec[b];
    const int cend  = g_csum[b * T_ + t];
    const int start = (t > 0) ? g_csum[b * T_ + t - 1] : 0;
    const int end   = cend < dec ? cend : dec;
    if (start >= end) return;             // warp-uniform exit

    // conv window scalars (warp-uniform broadcast loads)
    const int pbase = b * T_;
    const float pm1 = (t > 0)      ? __ldg(pitch  + pbase + t - 1) : 0.f;
    const float p0  =                __ldg(pitch  + pbase + t);
    const float pp1 = (t < T_ - 1) ? __ldg(pitch  + pbase + t + 1) : 0.f;
    const float em1 = (t > 0)      ? __ldg(energy + pbase + t - 1) : 0.f;
    const float e0  =                __ldg(energy + pbase + t);
    const float ep1 = (t < T_ - 1) ? __ldg(energy + pbase + t + 1) : 0.f;

    const float4 ev = __ldcs((const float4*)(enc + ((size_t)b * T_ + t) * H_ + c0));

    const float4 w0 = *(const float4*)(s_pw0 + c0);
    const float4 w1 = *(const float4*)(s_pw1 + c0);
    const float4 w2 = *(const float4*)(s_pw2 + c0);
    const float4 u0 = *(const float4*)(s_ew0 + c0);
    const float4 u1 = *(const float4*)(s_ew1 + c0);
    const float4 u2 = *(const float4*)(s_ew2 + c0);
    const float4 bi = *(const float4*)(s_bias + c0);

    float4 r;
    r.x = ev.x + bi.x + pm1 * w0.x + p0 * w1.x + pp1 * w2.x
               + em1 * u0.x + e0 * u1.x + ep1 * u2.x;
    r.y = ev.y + bi.y + pm1 * w0.y + p0 * w1.y + pp1 * w2.y
               + em1 * u0.y + e0 * u1.y + ep1 * u2.y;
    r.z = ev.z + bi.z + pm1 * w0.z + p0 * w1.z + pp1 * w2.z
               + em1 * u0.z + e0 * u1.z + ep1 * u2.z;
    r.w = ev.w + bi.w + pm1 * w0.w + p0 * w1.w + pp1 * w2.w
               + em1 * u0.w + e0 * u1.w + ep1 * u2.w;

    // stream the run: independent stores, consecutive rows
    float* outp = out + ((size_t)b * M_ + start) * H_ + c0;
    for (int j = start; j < end; ++j) {
        __stwt((float4*)outp, r);
        outp += H_;
    }
}

// ---------------------------------------------------------------------------
// Inputs: 0 enc [B,T,H] f32 | 1 pitch [B,1,T] | 2 energy [B,1,T]
//         3 pitch_w [H,1,3] | 4 pitch_b [H] | 5 energy_w [H,1,3] | 6 energy_b [H]
//         7 durations [B,T] i32
// Output: len_regulated [B,M,H] f32 followed by dec_lens [B] (as f32)
// ---------------------------------------------------------------------------
extern "C" void kernel_launch(void* const* d_in, const int* in_sizes, int n_in,
                              void* d_out, int out_size) {
    const float* enc    = (const float*)d_in[0];
    const float* pitch  = (const float*)d_in[1];
    const float* energy = (const float*)d_in[2];
    const float* pw     = (const float*)d_in[3];
    const float* pb     = (const float*)d_in[4];
    const float* ew     = (const float*)d_in[5];
    const float* eb     = (const float*)d_in[6];
    const int*   dur    = (const int*)d_in[7];
    float* out = (float*)d_out;

    prep_kernel<<<B_, T_>>>(dur, out);

    dim3 blk(96, 4);
    dim3 grid(SCAT_BLKS + ZERO_BLKS, B_);
    fused_kernel<<<grid, blk>>>(enc, pitch, energy, pw, pb, ew, eb, out);
}